// round 3
// baseline (speedup 1.0000x reference)
#include <cuda_runtime.h>
#include <cstdint>

#define BATCH 32
#define TT    2048
#define FF    64
#define HH    256
#define G3    768
#define OUTD  64
#define EPSF  1e-3f

#define CLUSTER 8
#define NCLUST  (BATCH/2)           // 16 clusters, 2 batches each
#define NCTA    (CLUSTER*NCLUST)    // 128 CTAs
#define COLS    96                  // gate columns per CTA (768/8)
#define THREADS 192                 // 6 warps: (kc in {0,1}) x (3 col-warps of 32)

typedef unsigned long long ull;

// ---- device scratch (no allocations allowed) ----
__device__ float g_xb1[(size_t)BATCH * TT * G3];   // LN(x)@k1 + b1[0]
__device__ float g_xb2[(size_t)BATCH * TT * G3];   // h1@k2 + b2[0]
__device__ float g_h2[BATCH * HH];                 // layer-2 final hidden

// ---- helpers ----
__device__ __forceinline__ uint32_t smem_u32(const void* p) {
    uint32_t a;
    asm("{ .reg .u64 t; cvta.to.shared.u64 t, %1; cvt.u32.u64 %0, t; }" : "=r"(a) : "l"(p));
    return a;
}
__device__ __forceinline__ void st_cluster_u64(uint32_t local_addr, ull v, uint32_t peer) {
    uint32_t ra;
    asm("mapa.shared::cluster.u32 %0, %1, %2;" : "=r"(ra) : "r"(local_addr), "r"(peer));
    asm volatile("st.shared::cluster.u64 [%0], %1;" :: "r"(ra), "l"(v) : "memory");
}
__device__ __forceinline__ void cluster_sync_() {
    asm volatile("barrier.cluster.arrive.aligned;" ::: "memory");
    asm volatile("barrier.cluster.wait.aligned;"   ::: "memory");
}
__device__ __forceinline__ uint32_t cluster_rank() {
    uint32_t r; asm("mov.u32 %0, %%cluster_ctarank;" : "=r"(r)); return r;
}
__device__ __forceinline__ float sigmf_(float x) { return 1.f / (1.f + expf(-x)); }

// ============================================================================
// Kernel 1: LayerNorm + input projection of layer 1.
//   g_xb1[b,t,:] = LN(x[b,t,:]) @ k1 + b1[0]
// 16 rows per block, 256 threads, grid = B*T/16.
// ============================================================================
__global__ void __launch_bounds__(256)
k_ln_proj(const float* __restrict__ x, const float* __restrict__ gamma,
          const float* __restrict__ beta, const float* __restrict__ k1,
          const float* __restrict__ b1)
{
    __shared__ float xs[16][64];
    const int tid = threadIdx.x;
    const int w = tid >> 5, l = tid & 31;
    const size_t rowbase = (size_t)blockIdx.x * 16;

    // LayerNorm: warp w handles rows 2w, 2w+1
    #pragma unroll
    for (int rr = 0; rr < 2; rr++) {
        const int r = 2 * w + rr;
        const float* xr = x + (rowbase + r) * FF;
        float v0 = xr[l], v1 = xr[l + 32];
        float s = v0 + v1;
        #pragma unroll
        for (int o = 16; o; o >>= 1) s += __shfl_xor_sync(0xFFFFFFFFu, s, o);
        const float mu = s * (1.f / 64.f);
        const float d0 = v0 - mu, d1 = v1 - mu;
        float q = d0 * d0 + d1 * d1;
        #pragma unroll
        for (int o = 16; o; o >>= 1) q += __shfl_xor_sync(0xFFFFFFFFu, q, o);
        const float rstd = rsqrtf(q * (1.f / 64.f) + EPSF);
        xs[r][l]      = d0 * rstd * gamma[l]      + beta[l];
        xs[r][l + 32] = d1 * rstd * gamma[l + 32] + beta[l + 32];
    }
    __syncthreads();

    // GEMM: each thread owns cols tid, tid+256, tid+512; 16 rows
    float acc[3][16];
    #pragma unroll
    for (int j = 0; j < 3; j++) {
        const float b = b1[tid + j * 256];
        #pragma unroll
        for (int r = 0; r < 16; r++) acc[j][r] = b;
    }
    for (int k = 0; k < 64; k++) {
        const float w0 = __ldg(k1 + k * G3 + tid);
        const float w1 = __ldg(k1 + k * G3 + tid + 256);
        const float w2 = __ldg(k1 + k * G3 + tid + 512);
        #pragma unroll
        for (int r = 0; r < 16; r++) {
            const float xv = xs[r][k];
            acc[0][r] = fmaf(xv, w0, acc[0][r]);
            acc[1][r] = fmaf(xv, w1, acc[1][r]);
            acc[2][r] = fmaf(xv, w2, acc[2][r]);
        }
    }
    #pragma unroll
    for (int r = 0; r < 16; r++) {
        float* o = g_xb1 + (rowbase + r) * G3;
        o[tid]       = acc[0][r];
        o[tid + 256] = acc[1][r];
        o[tid + 512] = acc[2][r];
    }
}

// ============================================================================
// Recurrent GRU kernel. Cluster of 8 CTAs handles 2 batches.
// CTA rank r owns gate columns gcol = gate*256 + r*32 + i  (i in [0,32), 3 gates).
// PROJ=true (layer 1): also computes g_xb2[t] = h1[t]@k2 + b2[0] fused in-loop.
// PROJ=false (layer 2): reads g_xb2, writes final h to g_h2.
// ============================================================================
template<bool PROJ>
__global__ void __launch_bounds__(THREADS) __cluster_dims__(CLUSTER, 1, 1)
k_gru(const float* __restrict__ rk, const float* __restrict__ bias,
      const float* __restrict__ kproj, const float* __restrict__ bproj)
{
    extern __shared__ float sm[];
    float* Wr   = sm;                                   // [256][96]
    float* Wk   = sm + 256 * COLS;                      // [256][96] (PROJ only)
    float* hbuf = sm + 256 * COLS * (PROJ ? 2 : 1);     // [2 parity][256][2 batch]
    float* xbb  = hbuf + 2 * 512;                       // [96][2]
    float* scR  = xbb + COLS * 2;                       // [2 kc][96][2]
    float* scK  = scR + 2 * COLS * 2;                   // [2 kc][96][2]
    float* rb   = scK + 2 * COLS * 2;                   // [96] recurrent bias slice
    float* kb   = rb + COLS;                            // [96] proj bias slice

    const int tid  = threadIdx.x;
    const uint32_t rank = cluster_rank();
    const int ci = blockIdx.x / CLUSTER;
    const int b0 = 2 * ci;

    const float* xbin = PROJ ? g_xb1 : g_xb2;

    // ---- stage weights and biases into SMEM ----
    for (int i = tid; i < 256 * COLS; i += THREADS) {
        const int k = i / COLS, c = i % COLS;
        const int gc = (c >> 5) * 256 + rank * 32 + (c & 31);
        Wr[i] = rk[k * G3 + gc];
        if (PROJ) Wk[i] = kproj[k * G3 + gc];
    }
    for (int c = tid; c < COLS; c += THREADS) {
        const int gc = (c >> 5) * 256 + rank * 32 + (c & 31);
        rb[c] = bias[G3 + gc];               // b[1][gc]
        if (PROJ) kb[c] = bproj[gc];         // b2[0][gc]
    }
    for (int i = tid; i < 2 * 512; i += THREADS) hbuf[i] = 0.f;
    cluster_sync_();

    // thread roles
    const int warp = tid >> 5, lane = tid & 31;
    const int kc = warp & 1;                 // k-half: [kc*128, kc*128+128)
    const int col = (warp >> 1) * 32 + lane; // 0..95
    const int kbase = kc * 128;

    // xb loader role: (lb, lc)
    const int lb = tid / COLS, lc = tid % COLS;   // lb in {0,1}
    const int gcl = (lc >> 5) * 256 + rank * 32 + (lc & 31);
    const float* xbp = xbin + ((size_t)(b0 + lb) * TT) * G3 + gcl;
    float* xbo = PROJ ? (g_xb2 + ((size_t)(b0 + lb) * TT) * G3 + gcl) : nullptr;

    int p = 0;
    const int TMAX = PROJ ? TT + 1 : TT;
    for (int t = 0; t < TMAX; t++) {
        const bool do_gate = (t < TT);
        float xv = 0.f;
        if (do_gate) xv = __ldg(xbp + (size_t)t * G3);   // prefetch; hidden by matvec

        // ---- matvec: rk @ h_prev (and k2 @ h_prev if PROJ) over this thread's k-half
        float arA0 = 0.f, arA1 = 0.f, arB0 = 0.f, arB1 = 0.f;
        float akA0 = 0.f, akA1 = 0.f, akB0 = 0.f, akB1 = 0.f;
        {
            const float* wr = Wr + kbase * COLS + col;
            const float* wk = Wk + kbase * COLS + col;
            const float4* hb4 = reinterpret_cast<const float4*>(hbuf + p * 512) + (kbase >> 1);
            #pragma unroll 8
            for (int kk = 0; kk < 128; kk += 2) {
                const float4 hv = hb4[kk >> 1];      // h[k](b0,b1), h[k+1](b0,b1)
                const float w0 = wr[0], w1 = wr[COLS];
                arA0 = fmaf(w0, hv.x, arA0);
                arA1 = fmaf(w0, hv.y, arA1);
                arB0 = fmaf(w1, hv.z, arB0);
                arB1 = fmaf(w1, hv.w, arB1);
                if (PROJ) {
                    const float u0 = wk[0], u1 = wk[COLS];
                    akA0 = fmaf(u0, hv.x, akA0);
                    akA1 = fmaf(u0, hv.y, akA1);
                    akB0 = fmaf(u1, hv.z, akB0);
                    akB1 = fmaf(u1, hv.w, akB1);
                    wk += 2 * COLS;
                }
                wr += 2 * COLS;
            }
        }
        scR[(kc * COLS + col) * 2 + 0] = arA0 + arB0;
        scR[(kc * COLS + col) * 2 + 1] = arA1 + arB1;
        if (PROJ) {
            scK[(kc * COLS + col) * 2 + 0] = akA0 + akB0;
            scK[(kc * COLS + col) * 2 + 1] = akA1 + akB1;
        }
        if (do_gate) xbb[lc * 2 + lb] = xv;
        __syncthreads();

        // ---- write xb2[t-1] (projection of h1[t-1], which the matvec just computed)
        if (PROJ && t > 0) {
            const float v = scK[lc * 2 + lb] + scK[(COLS + lc) * 2 + lb] + kb[lc];
            xbo[(size_t)(t - 1) * G3] = v;
        }

        // ---- gates + state update + cluster broadcast (32 threads, both batches)
        if (do_gate && tid < 32) {
            const int hi = tid;
            const float sZ0 = scR[hi * 2]            + scR[(COLS + hi) * 2]            + rb[hi];
            const float sZ1 = scR[hi * 2 + 1]        + scR[(COLS + hi) * 2 + 1]        + rb[hi];
            const float sR0 = scR[(32 + hi) * 2]     + scR[(COLS + 32 + hi) * 2]       + rb[32 + hi];
            const float sR1 = scR[(32 + hi) * 2 + 1] + scR[(COLS + 32 + hi) * 2 + 1]   + rb[32 + hi];
            const float sH0 = scR[(64 + hi) * 2]     + scR[(COLS + 64 + hi) * 2]       + rb[64 + hi];
            const float sH1 = scR[(64 + hi) * 2 + 1] + scR[(COLS + 64 + hi) * 2 + 1]   + rb[64 + hi];

            const int hg = rank * 32 + hi;
            const float hp0 = hbuf[p * 512 + hg * 2];
            const float hp1 = hbuf[p * 512 + hg * 2 + 1];

            const float z0 = sigmf_(xbb[hi * 2]            + sZ0);
            const float r0 = sigmf_(xbb[(32 + hi) * 2]     + sR0);
            const float hh0 = tanhf(xbb[(64 + hi) * 2]     + r0 * sH0);
            const float hn0 = z0 * hp0 + (1.f - z0) * hh0;

            const float z1 = sigmf_(xbb[hi * 2 + 1]        + sZ1);
            const float r1 = sigmf_(xbb[(32 + hi) * 2 + 1] + sR1);
            const float hh1 = tanhf(xbb[(64 + hi) * 2 + 1] + r1 * sH1);
            const float hn1 = z1 * hp1 + (1.f - z1) * hh1;

            const ull pk = ((ull)__float_as_uint(hn1) << 32) | (ull)__float_as_uint(hn0);
            const uint32_t la = smem_u32(hbuf + (p ^ 1) * 512 + hg * 2);
            #pragma unroll
            for (int pr = 0; pr < CLUSTER; pr++) st_cluster_u64(la, pk, (uint32_t)pr);

            if (!PROJ && t == TT - 1) {
                g_h2[b0 * HH + hg]       = hn0;
                g_h2[(b0 + 1) * HH + hg] = hn1;
            }
        }
        cluster_sync_();     // orders all DSMEM pushes before next step's reads
        p ^= 1;
    }
}

// ============================================================================
// Kernel 4: final dense.  out[b] = h2[b] @ wd + bd
// ============================================================================
__global__ void __launch_bounds__(64)
k_dense(const float* __restrict__ wd, const float* __restrict__ bd,
        float* __restrict__ out)
{
    __shared__ float hs[HH];
    const int b = blockIdx.x, o = threadIdx.x;
    for (int k = o; k < HH; k += 64) hs[k] = g_h2[b * HH + k];
    __syncthreads();
    float acc = bd[o];
    for (int k = 0; k < HH; k++) acc = fmaf(hs[k], __ldg(wd + k * OUTD + o), acc);
    out[b * OUTD + o] = acc;
}

// ============================================================================
extern "C" void kernel_launch(void* const* d_in, const int* in_sizes, int n_in,
                              void* d_out, int out_size)
{
    const float* x     = (const float*)d_in[0];
    const float* gamma = (const float*)d_in[1];
    const float* beta  = (const float*)d_in[2];
    const float* k1    = (const float*)d_in[3];
    const float* rk1   = (const float*)d_in[4];
    const float* b1    = (const float*)d_in[5];
    const float* k2    = (const float*)d_in[6];
    const float* rk2   = (const float*)d_in[7];
    const float* b2    = (const float*)d_in[8];
    const float* wd    = (const float*)d_in[9];
    const float* bd    = (const float*)d_in[10];
    float* out = (float*)d_out;

    const size_t extra = (2 * 512 + COLS * 2 + 2 * COLS * 2 + 2 * COLS * 2 + COLS + COLS);
    const size_t smem1 = (2 * 256 * COLS + extra) * sizeof(float);
    const size_t smem2 = (1 * 256 * COLS + extra) * sizeof(float);
    cudaFuncSetAttribute(k_gru<true>,  cudaFuncAttributeMaxDynamicSharedMemorySize, (int)smem1);
    cudaFuncSetAttribute(k_gru<false>, cudaFuncAttributeMaxDynamicSharedMemorySize, (int)smem2);

    k_ln_proj<<<BATCH * TT / 16, 256>>>(x, gamma, beta, k1, b1);
    k_gru<true><<<NCTA, THREADS, smem1>>>(rk1, b1, k2, b2);
    k_gru<false><<<NCTA, THREADS, smem2>>>(rk2, b2, nullptr, nullptr);
    k_dense<<<BATCH, 64>>>(wd, bd, out);
}